// round 6
// baseline (speedup 1.0000x reference)
#include <cuda_runtime.h>
#include <cuda_bf16.h>
#include <cuda_fp16.h>

#define H     128
#define BATCH 8
#define TQ    512
#define TK    512

// Device scratch (allocation-free rule: __device__ globals)
__device__ __align__(16) float   g_qp [BATCH * TQ * H];        // [b][q][h] f32
__device__ __align__(16) __half2 g_kph[BATCH * (H/2) * TK];    // [b][h/2][k] packed h-pairs

__device__ __forceinline__ __half2 tanh2(__half2 x) {
    unsigned xi = *(unsigned*)&x, yi;
    asm("tanh.approx.f16x2 %0, %1;" : "=r"(yi) : "r"(xi));
    return *(__half2*)&yi;
}

// ---------------------------------------------------------------------------
// Kernel 1: projections.
//   proj==0:  g_qp[b][t][h]  = queries @ Wa_w^T + Wa_b      (f32)
//   proj==1:  g_kph[b][h/2][t] = keys @ Ua_w^T + Ua_b       (half2 h-pairs)
// grid = (T/8, B, 2), block = 128 (one thread per output column h, 8 rows)
// ---------------------------------------------------------------------------
__global__ void __launch_bounds__(128) proj_kernel(
    const float* __restrict__ queries, const float* __restrict__ keys,
    const float* __restrict__ Wa_w, const float* __restrict__ Wa_b,
    const float* __restrict__ Ua_w, const float* __restrict__ Ua_b)
{
    const int tile = blockIdx.x;   // 64 tiles of 8 rows
    const int b    = blockIdx.y;
    const int proj = blockIdx.z;

    const float* x    = proj == 0 ? queries : keys;
    const float* W    = proj == 0 ? Wa_w    : Ua_w;
    const float* bias = proj == 0 ? Wa_b    : Ua_b;

    const int t0 = tile * 8;
    __shared__ __align__(16) float xs[8][H];
    __shared__ float sh[H][8];     // for h-pair packing (proj==1)

    const float4* xsrc = (const float4*)(x + (size_t)(b * 512 + t0) * H);
    #pragma unroll
    for (int i = threadIdx.x; i < 8 * H / 4; i += 128)
        ((float4*)xs)[i] = xsrc[i];
    __syncthreads();

    const int h = threadIdx.x;
    float acc[8];
    const float bv = bias[h];
    #pragma unroll
    for (int t = 0; t < 8; t++) acc[t] = bv;

    const float4* Wrow = (const float4*)(W + h * H);
    #pragma unroll 4
    for (int i = 0; i < H / 4; i++) {
        float4 w4 = Wrow[i];
        #pragma unroll
        for (int t = 0; t < 8; t++) {
            float4 xv = ((const float4*)xs[t])[i];
            acc[t] = fmaf(xv.x, w4.x, fmaf(xv.y, w4.y, fmaf(xv.z, w4.z, fmaf(xv.w, w4.w, acc[t]))));
        }
    }

    if (proj == 0) {
        #pragma unroll
        for (int t = 0; t < 8; t++)
            g_qp[(size_t)(b * TQ + t0 + t) * H + h] = acc[t];
    } else {
        #pragma unroll
        for (int t = 0; t < 8; t++) sh[h][t] = acc[t];
        __syncthreads();
        // Pack (h=2j, h=2j+1) into half2 per key: 512 outputs, 4 per thread
        __half2* dst = g_kph + (size_t)b * (H/2) * TK + t0;
        #pragma unroll
        for (int r = 0; r < 4; r++) {
            int idx = threadIdx.x + 128 * r;   // 0..511
            int t   = idx & 7;
            int j   = idx >> 3;                // h-pair 0..63
            dst[(size_t)j * TK + t] = __floats2half2_rn(sh[2*j][t], sh[2*j+1][t]);
        }
    }
}

// ---------------------------------------------------------------------------
// Kernel 2: scores + softmax. grid (TQ/4, B), block 128 (4 warps, 1 q/warp).
// Lane owns keys {64t + 2*lane + e}, t=0..7, e=0..1 -> 16 register slots.
// Inner loop over 64 h-pairs; tanh.approx.f16x2 = 2 tanh per MUFU instr.
// ---------------------------------------------------------------------------
__global__ void __launch_bounds__(128) score_kernel(
    const float* __restrict__ Va_w,
    float* __restrict__ w_out)     // (B, TQ, TK)
{
    __shared__ __align__(16) float4 qmeta[4][H/2];  // {q2 half2 bits, va0, va1, -}

    const int b    = blockIdx.y;
    const int wid  = threadIdx.x >> 5;
    const int lane = threadIdx.x & 31;
    const int q    = blockIdx.x * 4 + wid;

    {
        const float* qp = g_qp + (size_t)(b * TQ + q) * H;
        #pragma unroll
        for (int r = 0; r < 2; r++) {
            int j = lane + 32 * r;             // h-pair index 0..63
            __half2 q2 = __floats2half2_rn(qp[2*j], qp[2*j+1]);
            qmeta[wid][j] = make_float4(__uint_as_float(*(unsigned*)&q2),
                                        Va_w[2*j], Va_w[2*j+1], 0.f);
        }
    }
    __syncwarp();

    float a[16];
    #pragma unroll
    for (int i = 0; i < 16; i++) a[i] = 0.f;

    // base: keys (2*lane, 2*lane+1) -> one 8B LDG.64 per (h-pair, t)
    const uint2* kb = (const uint2*)(g_kph + (size_t)b * (H/2) * TK) + lane;

    #pragma unroll 2
    for (int j = 0; j < H/2; j++) {
        float4 meta = qmeta[wid][j];           // broadcast LDS.128
        unsigned qbits = __float_as_uint(meta.x);
        __half2  q2    = *(__half2*)&qbits;
        const uint2* kr = kb + j * (TK / 2);
        uint2 kk[8];
        #pragma unroll
        for (int t = 0; t < 8; t++) kk[t] = kr[t * 32];   // MLP=8 coalesced LDG.64
        #pragma unroll
        for (int t = 0; t < 8; t++) {
            __half2 k0 = *(__half2*)&kk[t].x;  // key 64t+2lane,   h {2j,2j+1}
            __half2 k1 = *(__half2*)&kk[t].y;  // key 64t+2lane+1, h {2j,2j+1}
            float2 f0 = __half22float2(tanh2(__hadd2(q2, k0)));
            float2 f1 = __half22float2(tanh2(__hadd2(q2, k1)));
            a[2*t]   = fmaf(meta.y, f0.x, a[2*t]);
            a[2*t]   = fmaf(meta.z, f0.y, a[2*t]);
            a[2*t+1] = fmaf(meta.y, f1.x, a[2*t+1]);
            a[2*t+1] = fmaf(meta.z, f1.y, a[2*t+1]);
        }
    }

    // ---- softmax in registers ----
    float m = a[0];
    #pragma unroll
    for (int i = 1; i < 16; i++) m = fmaxf(m, a[i]);
    #pragma unroll
    for (int o = 16; o > 0; o >>= 1)
        m = fmaxf(m, __shfl_xor_sync(0xffffffffu, m, o));

    float s = 0.f;
    #pragma unroll
    for (int i = 0; i < 16; i++) { a[i] = __expf(a[i] - m); s += a[i]; }
    #pragma unroll
    for (int o = 16; o > 0; o >>= 1)
        s += __shfl_xor_sync(0xffffffffu, s, o);

    const float inv = __fdividef(1.f, s);
    float* wrow = w_out + (size_t)(b * TQ + q) * TK;
    #pragma unroll
    for (int t = 0; t < 8; t++)
        *(float2*)(wrow + 64 * t + 2 * lane) =
            make_float2(a[2*t] * inv, a[2*t+1] * inv);
}

// ---------------------------------------------------------------------------
// Kernel 3: context = w @ keys. grid (TQ/8, B), block 128 (4 warps).
// Two queries per warp so each key float4 is amortized over 2 queries.
// ---------------------------------------------------------------------------
__global__ void __launch_bounds__(128) ctx_kernel(
    const float* __restrict__ keys,
    const float* __restrict__ w_in,    // (B, TQ, TK)
    float* __restrict__ ctx_out)       // (B, TQ, H)
{
    __shared__ float wsm[8][TK];

    const int b    = blockIdx.y;
    const int wid  = threadIdx.x >> 5;
    const int lane = threadIdx.x & 31;
    const int q0   = blockIdx.x * 8 + 2 * wid;

    {
        const float4* src = (const float4*)(w_in + (size_t)(b * TQ + q0) * TK);
        float4* dst = (float4*)&wsm[2 * wid][0];
        #pragma unroll
        for (int i = 0; i < 8; i++)
            dst[lane + 32 * i] = src[lane + 32 * i];
    }
    __syncwarp();

    float4 acc0 = make_float4(0.f, 0.f, 0.f, 0.f);
    float4 acc1 = make_float4(0.f, 0.f, 0.f, 0.f);
    const float4* kb = (const float4*)(keys + (size_t)b * TK * H) + lane;
    const float* w0 = wsm[2 * wid];
    const float* w1 = wsm[2 * wid + 1];
    #pragma unroll 8
    for (int key = 0; key < TK; key++) {
        float4 kv = kb[key * (H / 4)];           // coalesced LDG.128, L1/L2-hot
        float wa = w0[key];                      // broadcast LDS
        float wb = w1[key];
        acc0.x = fmaf(wa, kv.x, acc0.x); acc0.y = fmaf(wa, kv.y, acc0.y);
        acc0.z = fmaf(wa, kv.z, acc0.z); acc0.w = fmaf(wa, kv.w, acc0.w);
        acc1.x = fmaf(wb, kv.x, acc1.x); acc1.y = fmaf(wb, kv.y, acc1.y);
        acc1.z = fmaf(wb, kv.z, acc1.z); acc1.w = fmaf(wb, kv.w, acc1.w);
    }
    float4* crow = (float4*)(ctx_out + (size_t)(b * TQ + q0) * H);
    crow[lane]           = acc0;
    crow[lane + (H / 4)] = acc1;
}

// ---------------------------------------------------------------------------
extern "C" void kernel_launch(void* const* d_in, const int* in_sizes, int n_in,
                              void* d_out, int out_size)
{
    const float* queries = (const float*)d_in[0];
    const float* keys    = (const float*)d_in[1];
    const float* Wa_w    = (const float*)d_in[2];
    const float* Wa_b    = (const float*)d_in[3];
    const float* Ua_w    = (const float*)d_in[4];
    const float* Ua_b    = (const float*)d_in[5];
    const float* Va_w    = (const float*)d_in[6];
    // Va bias (d_in[7]) cancels in softmax -> unused.

    float* ctx_out = (float*)d_out;                     // (B, TQ, H)
    float* w_out   = ctx_out + BATCH * TQ * H;          // (B, TQ, TK)

    dim3 g1(512 / 8, BATCH, 2);
    proj_kernel<<<g1, 128>>>(queries, keys, Wa_w, Wa_b, Ua_w, Ua_b);

    dim3 g2(TQ / 4, BATCH);
    score_kernel<<<g2, 128>>>(Va_w, w_out);

    dim3 g3(TQ / 8, BATCH);
    ctx_kernel<<<g3, 128>>>(keys, w_out, ctx_out);
}

// round 7
// speedup vs baseline: 1.0551x; 1.0551x over previous
#include <cuda_runtime.h>
#include <cuda_bf16.h>
#include <cuda_fp16.h>

#define H     128
#define BATCH 8
#define TQ    512
#define TK    512

// Device scratch (allocation-free rule: __device__ globals)
__device__ __align__(16) float   g_qp [BATCH * TQ * H];        // [b][q][h] f32
__device__ __align__(16) __half2 g_kph[BATCH * (H/2) * TK];    // [b][h/2][k] packed h-pairs

__device__ __forceinline__ __half2 tanh2(__half2 x) {
    unsigned xi = *(unsigned*)&x, yi;
    asm("tanh.approx.f16x2 %0, %1;" : "=r"(yi) : "r"(xi));
    return *(__half2*)&yi;
}

// ---------------------------------------------------------------------------
// Kernel 1: projections (16-row tiles, reverted from 8 — better W reuse).
//   proj==0:  g_qp[b][t][h]    = queries @ Wa_w^T + Wa_b   (f32)
//   proj==1:  g_kph[b][h/2][t] = keys    @ Ua_w^T + Ua_b   (half2 h-pairs)
// grid = (T/16, B, 2), block = 128 (one thread per output column h)
// ---------------------------------------------------------------------------
__global__ void __launch_bounds__(128) proj_kernel(
    const float* __restrict__ queries, const float* __restrict__ keys,
    const float* __restrict__ Wa_w, const float* __restrict__ Wa_b,
    const float* __restrict__ Ua_w, const float* __restrict__ Ua_b)
{
    const int tile = blockIdx.x;   // 32 tiles of 16 rows
    const int b    = blockIdx.y;
    const int proj = blockIdx.z;

    const float* x    = proj == 0 ? queries : keys;
    const float* W    = proj == 0 ? Wa_w    : Ua_w;
    const float* bias = proj == 0 ? Wa_b    : Ua_b;

    const int t0 = tile * 16;
    __shared__ __align__(16) float xs[16][H];
    __shared__ float sh[H][16];    // for h-pair packing (proj==1)

    const float4* xsrc = (const float4*)(x + (size_t)(b * 512 + t0) * H);
    #pragma unroll
    for (int i = threadIdx.x; i < 16 * H / 4; i += 128)
        ((float4*)xs)[i] = xsrc[i];
    __syncthreads();

    const int h = threadIdx.x;
    float acc[16];
    const float bv = bias[h];
    #pragma unroll
    for (int t = 0; t < 16; t++) acc[t] = bv;

    const float4* Wrow = (const float4*)(W + h * H);
    #pragma unroll 4
    for (int i = 0; i < H / 4; i++) {
        float4 w4 = Wrow[i];
        #pragma unroll
        for (int t = 0; t < 16; t++) {
            float4 xv = ((const float4*)xs[t])[i];
            acc[t] = fmaf(xv.x, w4.x, fmaf(xv.y, w4.y, fmaf(xv.z, w4.z, fmaf(xv.w, w4.w, acc[t]))));
        }
    }

    if (proj == 0) {
        #pragma unroll
        for (int t = 0; t < 16; t++)
            g_qp[(size_t)(b * TQ + t0 + t) * H + h] = acc[t];
    } else {
        #pragma unroll
        for (int t = 0; t < 16; t++) sh[h][t] = acc[t];
        __syncthreads();
        // Pack (h=2j, h=2j+1) into half2 per key: 1024 outputs, 8 per thread
        __half2* dst = g_kph + (size_t)b * (H/2) * TK + t0;
        #pragma unroll
        for (int r = 0; r < 8; r++) {
            int idx = threadIdx.x + 128 * r;   // 0..1023
            int t   = idx & 15;
            int j   = idx >> 4;                // h-pair 0..63
            dst[(size_t)j * TK + t] = __floats2half2_rn(sh[2*j][t], sh[2*j+1][t]);
        }
    }
}

// ---------------------------------------------------------------------------
// Kernel 2: scores + softmax. grid (TQ/4, B), block 128 (4 warps, 1 q/warp).
// Lane owns keys {64t + 2*lane + e}. Pure half2 datapath in the hot loop:
//   HADD2 -> tanh.f16x2 (MUFU) -> HFMA2 (fma pipe). NO per-term F2F.
// half2 partial sums flushed to f32 every 8 h-pairs (accuracy guard).
// ---------------------------------------------------------------------------
__global__ void __launch_bounds__(128) score_kernel(
    const float* __restrict__ Va_w,
    float* __restrict__ w_out)     // (B, TQ, TK)
{
    __shared__ __align__(8) float2 qm[4][H/2];   // per warp: {q2 bits, va2 bits}

    const int b    = blockIdx.y;
    const int wid  = threadIdx.x >> 5;
    const int lane = threadIdx.x & 31;
    const int q    = blockIdx.x * 4 + wid;

    {
        const float* qp = g_qp + (size_t)(b * TQ + q) * H;
        #pragma unroll
        for (int r = 0; r < 2; r++) {
            int j = lane + 32 * r;             // h-pair index 0..63
            __half2 q2  = __floats2half2_rn(qp[2*j],   qp[2*j+1]);
            __half2 va2 = __floats2half2_rn(Va_w[2*j], Va_w[2*j+1]);
            qm[wid][j] = make_float2(__uint_as_float(*(unsigned*)&q2),
                                     __uint_as_float(*(unsigned*)&va2));
        }
    }
    __syncwarp();

    float a[16];
    #pragma unroll
    for (int i = 0; i < 16; i++) a[i] = 0.f;

    const uint2* kb = (const uint2*)(g_kph + (size_t)b * (H/2) * TK) + lane;

    #pragma unroll 1
    for (int jb = 0; jb < 8; jb++) {           // 8 blocks of 8 h-pairs
        __half2 acc2[16];
        #pragma unroll
        for (int i = 0; i < 16; i++) acc2[i] = __half2half2(__float2half(0.f));

        #pragma unroll
        for (int j2 = 0; j2 < 8; j2++) {
            int j = jb * 8 + j2;
            float2 meta = qm[wid][j];          // broadcast LDS.64
            unsigned qb = __float_as_uint(meta.x);
            unsigned vb = __float_as_uint(meta.y);
            __half2 q2  = *(__half2*)&qb;
            __half2 va2 = *(__half2*)&vb;

            const uint2* kr = kb + j * (TK / 2);
            uint2 kk[8];
            #pragma unroll
            for (int t = 0; t < 8; t++) kk[t] = kr[t * 32];   // MLP=8 LDG.64
            #pragma unroll
            for (int t = 0; t < 8; t++) {
                __half2 k0 = *(__half2*)&kk[t].x;
                __half2 k1 = *(__half2*)&kk[t].y;
                acc2[2*t]   = __hfma2(va2, tanh2(__hadd2(q2, k0)), acc2[2*t]);
                acc2[2*t+1] = __hfma2(va2, tanh2(__hadd2(q2, k1)), acc2[2*t+1]);
            }
        }
        #pragma unroll
        for (int i = 0; i < 16; i++) {
            float2 f = __half22float2(acc2[i]);
            a[i] += f.x + f.y;                 // fold even/odd-h partial sums
        }
    }

    // ---- softmax in registers ----
    float m = a[0];
    #pragma unroll
    for (int i = 1; i < 16; i++) m = fmaxf(m, a[i]);
    #pragma unroll
    for (int o = 16; o > 0; o >>= 1)
        m = fmaxf(m, __shfl_xor_sync(0xffffffffu, m, o));

    float s = 0.f;
    #pragma unroll
    for (int i = 0; i < 16; i++) { a[i] = __expf(a[i] - m); s += a[i]; }
    #pragma unroll
    for (int o = 16; o > 0; o >>= 1)
        s += __shfl_xor_sync(0xffffffffu, s, o);

    const float inv = __fdividef(1.f, s);
    float* wrow = w_out + (size_t)(b * TQ + q) * TK;
    #pragma unroll
    for (int t = 0; t < 8; t++)
        *(float2*)(wrow + 64 * t + 2 * lane) =
            make_float2(a[2*t] * inv, a[2*t+1] * inv);
}

// ---------------------------------------------------------------------------
// Kernel 3: context = w @ keys. grid (TQ/8, B), block 128 (4 warps).
// Two queries per warp so each key float4 is amortized over 2 queries.
// ---------------------------------------------------------------------------
__global__ void __launch_bounds__(128) ctx_kernel(
    const float* __restrict__ keys,
    const float* __restrict__ w_in,    // (B, TQ, TK)
    float* __restrict__ ctx_out)       // (B, TQ, H)
{
    __shared__ float wsm[8][TK];

    const int b    = blockIdx.y;
    const int wid  = threadIdx.x >> 5;
    const int lane = threadIdx.x & 31;
    const int q0   = blockIdx.x * 8 + 2 * wid;

    {
        const float4* src = (const float4*)(w_in + (size_t)(b * TQ + q0) * TK);
        float4* dst = (float4*)&wsm[2 * wid][0];
        #pragma unroll
        for (int i = 0; i < 8; i++)
            dst[lane + 32 * i] = src[lane + 32 * i];
    }
    __syncwarp();

    float4 acc0 = make_float4(0.f, 0.f, 0.f, 0.f);
    float4 acc1 = make_float4(0.f, 0.f, 0.f, 0.f);
    const float4* kb = (const float4*)(keys + (size_t)b * TK * H) + lane;
    const float* w0 = wsm[2 * wid];
    const float* w1 = wsm[2 * wid + 1];
    #pragma unroll 8
    for (int key = 0; key < TK; key++) {
        float4 kv = kb[key * (H / 4)];           // coalesced LDG.128, L1/L2-hot
        float wa = w0[key];                      // broadcast LDS
        float wb = w1[key];
        acc0.x = fmaf(wa, kv.x, acc0.x); acc0.y = fmaf(wa, kv.y, acc0.y);
        acc0.z = fmaf(wa, kv.z, acc0.z); acc0.w = fmaf(wa, kv.w, acc0.w);
        acc1.x = fmaf(wb, kv.x, acc1.x); acc1.y = fmaf(wb, kv.y, acc1.y);
        acc1.z = fmaf(wb, kv.z, acc1.z); acc1.w = fmaf(wb, kv.w, acc1.w);
    }
    float4* crow = (float4*)(ctx_out + (size_t)(b * TQ + q0) * H);
    crow[lane]           = acc0;
    crow[lane + (H / 4)] = acc1;
}

// ---------------------------------------------------------------------------
extern "C" void kernel_launch(void* const* d_in, const int* in_sizes, int n_in,
                              void* d_out, int out_size)
{
    const float* queries = (const float*)d_in[0];
    const float* keys    = (const float*)d_in[1];
    const float* Wa_w    = (const float*)d_in[2];
    const float* Wa_b    = (const float*)d_in[3];
    const float* Ua_w    = (const float*)d_in[4];
    const float* Ua_b    = (const float*)d_in[5];
    const float* Va_w    = (const float*)d_in[6];
    // Va bias (d_in[7]) cancels in softmax -> unused.

    float* ctx_out = (float*)d_out;                     // (B, TQ, H)
    float* w_out   = ctx_out + BATCH * TQ * H;          // (B, TQ, TK)

    dim3 g1(512 / 16, BATCH, 2);
    proj_kernel<<<g1, 128>>>(queries, keys, Wa_w, Wa_b, Ua_w, Ua_b);

    dim3 g2(TQ / 4, BATCH);
    score_kernel<<<g2, 128>>>(Va_w, w_out);

    dim3 g3(TQ / 8, BATCH);
    ctx_kernel<<<g3, 128>>>(keys, w_out, ctx_out);
}